// round 15
// baseline (speedup 1.0000x reference)
#include <cuda_runtime.h>
#include <cuda_bf16.h>
#include <math.h>
#include <stdint.h>

#define BB 64
#define TT 64
#define AA 64
#define HH 1024
#define CC 16

#define NT 128     // N cols per CTA
#define KC 32      // K floats per chunk

#define KSPLIT 32
#define TAU_KB (HH / KSPLIT)   // 32

// mma kernel dynamic smem layout (bytes)
#define A_PL   5120                    // 64 rows * 80 B
#define B_PL   8704                    // 32 rows * 272 B
#define BUF_SZ (2 * A_PL + 2 * B_PL)   // 27648
#define SMEM_SZ (2 * BUF_SZ)           // 55296

// Scratch (device globals; no runtime allocation)
__device__ __align__(16) __nv_bfloat16 g_a0h[BB * TT * AA], g_a0l[BB * TT * AA];
__device__ __align__(16) __nv_bfloat16 g_a1h[BB * TT * HH], g_a1l[BB * TT * HH];
__device__ __align__(16) __nv_bfloat16 g_a2h[BB * TT * HH], g_a2l[BB * TT * HH];
__device__ __align__(16) __nv_bfloat16 g_w1h[CC * AA * HH], g_w1l[CC * AA * HH];
__device__ __align__(16) __nv_bfloat16 g_w2h[CC * HH * HH], g_w2l[CC * HH * HH];
__device__ __align__(16) __nv_bfloat16 g_w3h[CC * HH * HH], g_w3l[CC * HH * HH];
__device__ float g_tauc[BB * HH];
__device__ float g_tau[BB * HH];
__device__ float g_part[KSPLIT * BB * HH];
__device__ int   g_cat_cnt[CC];
__device__ int   g_cat_list[CC * BB];

// ---------------- helpers ----------------
__device__ __forceinline__ uint32_t smem_u32(const void* p) {
    uint32_t a;
    asm("{ .reg .u64 t; cvta.to.shared.u64 t, %1; cvt.u32.u64 %0, t; }"
        : "=r"(a) : "l"(p));
    return a;
}
__device__ __forceinline__ void split_pair(float x, float y, uint32_t& h, uint32_t& l) {
    __nv_bfloat162 hb = __floats2bfloat162_rn(x, y);   // low 16 = x
    float hx = __bfloat162float(hb.x);
    float hy = __bfloat162float(hb.y);
    __nv_bfloat162 lb = __floats2bfloat162_rn(x - hx, y - hy);
    h = *reinterpret_cast<uint32_t*>(&hb);
    l = *reinterpret_cast<uint32_t*>(&lb);
}
__device__ __forceinline__ void mma_bf16(float* c, const uint32_t* a, uint32_t b0, uint32_t b1) {
    asm volatile(
        "mma.sync.aligned.m16n8k16.row.col.f32.bf16.bf16.f32 "
        "{%0,%1,%2,%3}, {%4,%5,%6,%7}, {%8,%9}, {%0,%1,%2,%3};"
        : "+f"(c[0]), "+f"(c[1]), "+f"(c[2]), "+f"(c[3])
        : "r"(a[0]), "r"(a[1]), "r"(a[2]), "r"(a[3]), "r"(b0), "r"(b1));
}
__device__ __forceinline__ void ldsm_x4(uint32_t* r, uint32_t addr) {
    asm volatile("ldmatrix.sync.aligned.m8n8.x4.shared.b16 {%0,%1,%2,%3}, [%4];"
                 : "=r"(r[0]), "=r"(r[1]), "=r"(r[2]), "=r"(r[3]) : "r"(addr));
}
__device__ __forceinline__ void ldsm_x4_t(uint32_t* r, uint32_t addr) {
    asm volatile("ldmatrix.sync.aligned.m8n8.x4.trans.shared.b16 {%0,%1,%2,%3}, [%4];"
                 : "=r"(r[0]), "=r"(r[1]), "=r"(r[2]), "=r"(r[3]) : "r"(addr));
}
__device__ __forceinline__ void cp_async16(uint32_t s, const void* g) {
    asm volatile("cp.async.ca.shared.global [%0], [%1], 16;" :: "r"(s), "l"(g));
}
#define CP_COMMIT() asm volatile("cp.async.commit_group;" ::: "memory")
#define CP_WAIT(n)  asm volatile("cp.async.wait_group %0;" :: "n"(n) : "memory")

// ---------------------------------------------------------------------------
// device bodies (verbatim logic from the R14-proven kernels)
// ---------------------------------------------------------------------------
__device__ void dev_prep(const int* __restrict__ cat_ids) {
    int c = threadIdx.x;
    if (c >= CC) return;
    int cnt = 0;
    for (int b = 0; b < BB; ++b)
        if (cat_ids[b] == c) g_cat_list[c * BB + cnt++] = b;
    g_cat_cnt[c] = cnt;
}

__device__ void dev_tau1(int b, const int* __restrict__ timesteps) {
    const int tid = threadIdx.x;
    const float t = (float)timesteps[b];
    const int half = HH / 2;
    const float scale = logf(10000.0f) / (float)half;
    for (int d = tid; d < HH; d += 256) {
        int j = (d < half) ? d : (d - half);
        float f = t * expf(-(float)j * scale);
        g_tau[b * HH + d] = (d < half) ? sinf(f) : cosf(f);
    }
}

__device__ void dev_actconv(int blk, const float* __restrict__ actions) {
    #pragma unroll
    for (int r = 0; r < 4; ++r) {
        int i = blk * 1024 + r * 256 + threadIdx.x;   // pair index, 131072 total
        float x = actions[2 * i], y = actions[2 * i + 1];
        uint32_t h, l;
        split_pair(x, y, h, l);
        ((uint32_t*)g_a0h)[i] = h;
        ((uint32_t*)g_a0l)[i] = l;
    }
}

// wconv: flat block id in [0, nbpc*CC); per-cat grid-stride over quads.
__device__ void dev_wconv(int flat, int nbpc,
                          const float* __restrict__ src,
                          __nv_bfloat16* __restrict__ dh,
                          __nv_bfloat16* __restrict__ dl,
                          size_t src_cat_stride, size_t dst_cat_stride,
                          int nquads) {
    const int cat = flat / nbpc;
    const int bx  = flat % nbpc;
    const float4* s = (const float4*)(src + cat * src_cat_stride);
    uint2* oh = (uint2*)(dh + cat * dst_cat_stride);
    uint2* ol = (uint2*)(dl + cat * dst_cat_stride);
    const int stride = nbpc * 256;
    for (int i = bx * 256 + threadIdx.x; i < nquads; i += stride) {
        float4 v = s[i];
        uint32_t h0, l0, h1, l1;
        split_pair(v.x, v.y, h0, l0);
        split_pair(v.z, v.w, h1, l1);
        oh[i] = make_uint2(h0, h1);
        ol[i] = make_uint2(l0, l1);
    }
}

// tau2 @256 threads: flat in [0,1024): bx = flat&1, cat = (flat>>1)&15, z = flat>>5
__device__ void dev_tau2(int flat, const float* __restrict__ W2, float* ts /*[8*TAU_KB]*/) {
    const int bx  = flat & 1;
    const int cat = (flat >> 1) & 15;
    const int z   = flat >> 5;
    const int tid = threadIdx.x;
    const int n2  = bx * 256 + tid;          // float2 column, 0..511
    const int cnt = g_cat_cnt[cat];
    if (cnt == 0) return;

    const int k0 = z * TAU_KB;
    const float* Wp = W2 + (size_t)cat * 2 * HH * HH
                         + (size_t)(HH + k0) * HH + 2 * n2;

    for (int base = 0; base < cnt; base += 8) {
        int nb = min(8, cnt - base);
        __syncthreads();
        for (int bl = 0; bl < nb; ++bl) {
            int bb = g_cat_list[cat * BB + base + bl];
            for (int d = tid; d < TAU_KB; d += 256)
                ts[bl * TAU_KB + d] = g_tau[bb * HH + k0 + d];
        }
        __syncthreads();
        float2 acc[8];
        #pragma unroll
        for (int bl = 0; bl < 8; ++bl) acc[bl] = make_float2(0.f, 0.f);
        #pragma unroll 4
        for (int k = 0; k < TAU_KB; ++k) {
            float2 w = *(const float2*)&Wp[(size_t)k * HH];
            #pragma unroll
            for (int bl = 0; bl < 8; ++bl) {
                acc[bl].x = fmaf(ts[bl * TAU_KB + k], w.x, acc[bl].x);
                acc[bl].y = fmaf(ts[bl * TAU_KB + k], w.y, acc[bl].y);
            }
        }
        for (int bl = 0; bl < nb; ++bl) {
            int bb = g_cat_list[cat * BB + base + bl];
            *(float2*)&g_part[((size_t)z * BB + bb) * HH + 2 * n2] = acc[bl];
        }
    }
}

// v2 split-bf16 mma layer body (R14-proven), nt/b passed explicitly.
template <int K, int ACT, int ADDMODE, int OUTMODE>
__device__ void dev_layer(int nt, int b,
          const __nv_bfloat16* __restrict__ Ahp,
          const __nv_bfloat16* __restrict__ Alp,
          const __nv_bfloat16* __restrict__ Whp,
          const __nv_bfloat16* __restrict__ Wlp,
          size_t wstride,
          const float* __restrict__ addv,
          const int* __restrict__ cat_ids,
          float* __restrict__ outf,
          __nv_bfloat16* __restrict__ outh,
          __nv_bfloat16* __restrict__ outl,
          char* sm) {
    const uint32_t smb = smem_u32(sm);
    const int tid  = threadIdx.x;
    const int lane = tid & 31;
    const int warp = tid >> 5;
    const int wm   = warp >> 2;   // 0..1
    const int wn   = warp & 3;    // 0..3
    const int c    = cat_ids[b];

    const __nv_bfloat16* Ap[2] = {Ahp + (size_t)b * 64 * K,
                                  Alp + (size_t)b * 64 * K};
    const __nv_bfloat16* Wp[2] = {Whp + (size_t)c * wstride + nt * NT,
                                  Wlp + (size_t)c * wstride + nt * NT};

    float acc[2][4][4];
    #pragma unroll
    for (int i = 0; i < 2; ++i)
        #pragma unroll
        for (int j = 0; j < 4; ++j)
            #pragma unroll
            for (int q = 0; q < 4; ++q) acc[i][j][q] = 0.0f;

    constexpr int NCHUNK = K / KC;

    auto issue = [&](int k0, int buf) {
        const uint32_t base = smb + buf * BUF_SZ;
        #pragma unroll
        for (int r = 0; r < 2; ++r) {
            int i = tid + r * 256;
            int p = i >> 8, rem = i & 255, m = rem >> 2, it = rem & 3;
            cp_async16(base + p * A_PL + m * 80 + it * 16,
                       Ap[p] + (size_t)m * K + k0 + it * 8);
        }
        #pragma unroll
        for (int r = 0; r < 4; ++r) {
            int i = tid + r * 256;
            int p = i >> 9, rem = i & 511, k = rem >> 4, it = rem & 15;
            cp_async16(base + 2 * A_PL + p * B_PL + k * 272 + it * 16,
                       Wp[p] + (size_t)(k0 + k) * HH + it * 8);
        }
    };

    const int l15 = lane & 15, g16 = lane >> 4;

    issue(0, 0); CP_COMMIT();

    for (int ch = 0; ch < NCHUNK; ++ch) {
        const int cur = ch & 1;
        if (ch + 1 < NCHUNK) {
            issue((ch + 1) * KC, cur ^ 1); CP_COMMIT();
            CP_WAIT(1);
        } else {
            CP_WAIT(0);
        }
        __syncthreads();

        const uint32_t aHi = smb + cur * BUF_SZ;
        const uint32_t aLo = aHi + A_PL;
        const uint32_t bHi = aHi + 2 * A_PL;
        const uint32_t bLo = bHi + B_PL;
        #pragma unroll
        for (int t = 0; t < 2; ++t) {
            uint32_t Ahf[2][4], Alf[2][4];
            #pragma unroll
            for (int ms = 0; ms < 2; ++ms) {
                uint32_t abyte = (wm * 32 + ms * 16 + l15) * 80 + t * 32 + g16 * 16;
                ldsm_x4(Ahf[ms], aHi + abyte);
                ldsm_x4(Alf[ms], aLo + abyte);
            }
            uint32_t Bh[2][4], Bl[2][4];
            #pragma unroll
            for (int nfp = 0; nfp < 2; ++nfp) {
                int kr = t * 16 + l15;
                uint32_t bbyte = kr * 272 + (wn * 32 + nfp * 16 + g16 * 8) * 2;
                ldsm_x4_t(Bh[nfp], bHi + bbyte);
                ldsm_x4_t(Bl[nfp], bLo + bbyte);
            }
            #pragma unroll
            for (int nf = 0; nf < 4; ++nf) {
                uint32_t bh0 = Bh[nf >> 1][(nf & 1) * 2];
                uint32_t bh1 = Bh[nf >> 1][(nf & 1) * 2 + 1];
                uint32_t bl0 = Bl[nf >> 1][(nf & 1) * 2];
                uint32_t bl1 = Bl[nf >> 1][(nf & 1) * 2 + 1];
                #pragma unroll
                for (int ms = 0; ms < 2; ++ms) {
                    mma_bf16(acc[ms][nf], Ahf[ms], bh0, bh1);   // hi*hi
                    mma_bf16(acc[ms][nf], Ahf[ms], bl0, bl1);   // hi*lo
                    mma_bf16(acc[ms][nf], Alf[ms], bh0, bh1);   // lo*hi
                }
            }
        }
        __syncthreads();
    }

    const float* addp = (ADDMODE == 0) ? (addv + (size_t)c * HH)
                                       : (addv + (size_t)b * HH);
    const int lr = lane >> 2;
    const int lc = lane & 3;
    #pragma unroll
    for (int ms = 0; ms < 2; ++ms) {
        int r0 = wm * 32 + ms * 16 + lr;
        #pragma unroll
        for (int nf = 0; nf < 4; ++nf) {
            int ncol = nt * NT + wn * 32 + nf * 8 + lc * 2;
            float bv0 = addp[ncol], bv1 = addp[ncol + 1];
            float v0 = acc[ms][nf][0] + bv0;
            float v1 = acc[ms][nf][1] + bv1;
            float v2 = acc[ms][nf][2] + bv0;
            float v3 = acc[ms][nf][3] + bv1;
            if (ACT == 1) {
                v0 = v0 / (1.0f + expf(-v0));
                v1 = v1 / (1.0f + expf(-v1));
                v2 = v2 / (1.0f + expf(-v2));
                v3 = v3 / (1.0f + expf(-v3));
            }
            size_t o0 = ((size_t)b * TT + r0)     * HH + ncol;
            size_t o1 = ((size_t)b * TT + r0 + 8) * HH + ncol;
            if (OUTMODE == 0) {
                *(float2*)&outf[o0] = make_float2(v0, v1);
                *(float2*)&outf[o1] = make_float2(v2, v3);
            } else {
                uint32_t h, l;
                split_pair(v0, v1, h, l);
                *(uint32_t*)&outh[o0] = h;
                *(uint32_t*)&outl[o0] = l;
                split_pair(v2, v3, h, l);
                *(uint32_t*)&outh[o1] = h;
                *(uint32_t*)&outl[o1] = l;
            }
        }
    }
}

// ---------------------------------------------------------------------------
// Launch A: prep | tau1 | actconv | wconv1.  grid(449), 256 thr.
// ---------------------------------------------------------------------------
__global__ void stepA_kernel(const int* __restrict__ cat_ids,
                             const int* __restrict__ timesteps,
                             const float* __restrict__ actions,
                             const float* __restrict__ W1) {
    const int x = blockIdx.x;
    if (x == 0) {
        dev_prep(cat_ids);
    } else if (x < 65) {
        dev_tau1(x - 1, timesteps);
    } else if (x < 193) {
        dev_actconv(x - 65, actions);
    } else {
        dev_wconv(x - 193, 16, W1, g_w1h, g_w1l,
                  (size_t)AA * HH, (size_t)AA * HH, AA * HH / 4);
    }
}

// ---------------------------------------------------------------------------
// Launch C: layer1 | wconv2 | tau2.  grid(56, 64), 256 thr, dyn smem.
// ---------------------------------------------------------------------------
__global__ void __launch_bounds__(256, 3)
stepC_kernel(const float* __restrict__ W2,
             const float* __restrict__ b1,
             const int* __restrict__ cat_ids) {
    extern __shared__ char sm[];
    const int x = blockIdx.x, y = blockIdx.y;
    if (x < 8) {
        dev_layer<AA, 0, 0, 1>(x, y, g_a0h, g_a0l, g_w1h, g_w1l,
                               (size_t)AA * HH, b1, cat_ids,
                               nullptr, g_a1h, g_a1l, sm);
    } else if (x < 40) {
        dev_wconv((x - 8) * 64 + y, 128, W2, g_w2h, g_w2l,
                  (size_t)2 * HH * HH, (size_t)HH * HH, HH * HH / 4);
    } else {
        dev_tau2((x - 40) * 64 + y, W2, (float*)sm);
    }
}

// ---------------------------------------------------------------------------
// Launch D: tau3 reduce.  grid(4, 64), 256 thr.
// ---------------------------------------------------------------------------
__global__ void tau3_kernel(const int* __restrict__ cat_ids,
                            const float* __restrict__ b2) {
    const int b = blockIdx.y;
    const int n = blockIdx.x * 256 + threadIdx.x;
    const int c = cat_ids[b];
    float s = b2[c * HH + n];
    #pragma unroll
    for (int z = 0; z < KSPLIT; ++z)
        s += g_part[((size_t)z * BB + b) * HH + n];
    g_tauc[b * HH + n] = s;
}

// ---------------------------------------------------------------------------
// Launch E: layer2 | wconv3.  grid(40, 64), 256 thr, dyn smem.
// ---------------------------------------------------------------------------
__global__ void __launch_bounds__(256, 3)
stepE_kernel(const float* __restrict__ W3,
             const int* __restrict__ cat_ids) {
    extern __shared__ char sm[];
    const int x = blockIdx.x, y = blockIdx.y;
    if (x < 8) {
        dev_layer<HH, 1, 1, 1>(x, y, g_a1h, g_a1l, g_w2h, g_w2l,
                               (size_t)HH * HH, g_tauc, cat_ids,
                               nullptr, g_a2h, g_a2l, sm);
    } else {
        dev_wconv((x - 8) * 64 + y, 128, W3, g_w3h, g_w3l,
                  (size_t)HH * HH, (size_t)HH * HH, HH * HH / 4);
    }
}

// ---------------------------------------------------------------------------
// Launch F: layer3.  grid(8, 64), 256 thr, dyn smem.
// ---------------------------------------------------------------------------
__global__ void __launch_bounds__(256, 3)
stepF_kernel(const float* __restrict__ b3,
             const int* __restrict__ cat_ids,
             float* __restrict__ out) {
    extern __shared__ char sm[];
    dev_layer<HH, 0, 0, 0>(blockIdx.x, blockIdx.y, g_a2h, g_a2l, g_w3h, g_w3l,
                           (size_t)HH * HH, b3, cat_ids,
                           out, nullptr, nullptr, sm);
}

extern "C" void kernel_launch(void* const* d_in, const int* in_sizes, int n_in,
                              void* d_out, int out_size) {
    const float* actions   = (const float*)d_in[0];
    const int*   timesteps = (const int*)d_in[1];
    const int*   cat_ids   = (const int*)d_in[2];
    const float* W1 = (const float*)d_in[3];
    const float* b1 = (const float*)d_in[4];
    const float* W2 = (const float*)d_in[5];
    const float* b2 = (const float*)d_in[6];
    const float* W3 = (const float*)d_in[7];
    const float* b3 = (const float*)d_in[8];
    float* out = (float*)d_out;

    cudaFuncSetAttribute(stepC_kernel,
                         cudaFuncAttributeMaxDynamicSharedMemorySize, SMEM_SZ);
    cudaFuncSetAttribute(stepE_kernel,
                         cudaFuncAttributeMaxDynamicSharedMemorySize, SMEM_SZ);
    cudaFuncSetAttribute(stepF_kernel,
                         cudaFuncAttributeMaxDynamicSharedMemorySize, SMEM_SZ);

    // A: prep | tau1 | actconv | wconv1
    stepA_kernel<<<449, 256>>>(cat_ids, timesteps, actions, W1);

    // C: layer1 | wconv2 | tau2
    stepC_kernel<<<dim3(56, 64), 256, SMEM_SZ>>>(W2, b1, cat_ids);

    // D: tau3
    tau3_kernel<<<dim3(4, 64), 256>>>(cat_ids, b2);

    // E: layer2 | wconv3
    stepE_kernel<<<dim3(40, 64), 256, SMEM_SZ>>>(W3, cat_ids);

    // F: layer3
    stepF_kernel<<<dim3(8, 64), 256, SMEM_SZ>>>(b3, cat_ids, out);
}

// round 16
// speedup vs baseline: 1.2339x; 1.2339x over previous
#include <cuda_runtime.h>
#include <cuda_bf16.h>
#include <math.h>
#include <stdint.h>

#define BB 64
#define TT 64
#define AA 64
#define HH 1024
#define CC 16

#define NT 128     // N cols per CTA
#define KC 32      // K floats per chunk

#define KSPLIT 32
#define TAU_KB (HH / KSPLIT)   // 32

// Scratch (device globals; no runtime allocation)
__device__ __align__(16) __nv_bfloat16 g_a0h[BB * TT * AA], g_a0l[BB * TT * AA];
__device__ __align__(16) __nv_bfloat16 g_a1h[BB * TT * HH], g_a1l[BB * TT * HH];
__device__ __align__(16) __nv_bfloat16 g_a2h[BB * TT * HH], g_a2l[BB * TT * HH];
__device__ float g_tauc[BB * HH];
__device__ float g_tau[BB * HH];
__device__ float g_part[KSPLIT * BB * HH];
__device__ int   g_cat_cnt[CC];
__device__ int   g_cat_list[CC * BB];

// ---------------- helpers ----------------
__device__ __forceinline__ uint32_t smem_u32(const void* p) {
    uint32_t a;
    asm("{ .reg .u64 t; cvta.to.shared.u64 t, %1; cvt.u32.u64 %0, t; }"
        : "=r"(a) : "l"(p));
    return a;
}
__device__ __forceinline__ void split_pair(float x, float y, uint32_t& h, uint32_t& l) {
    __nv_bfloat162 hb = __floats2bfloat162_rn(x, y);   // low 16 = x
    float hx = __bfloat162float(hb.x);
    float hy = __bfloat162float(hb.y);
    __nv_bfloat162 lb = __floats2bfloat162_rn(x - hx, y - hy);
    h = *reinterpret_cast<uint32_t*>(&hb);
    l = *reinterpret_cast<uint32_t*>(&lb);
}
__device__ __forceinline__ void mma_bf16(float* c, const uint32_t* a, uint32_t b0, uint32_t b1) {
    asm volatile(
        "mma.sync.aligned.m16n8k16.row.col.f32.bf16.bf16.f32 "
        "{%0,%1,%2,%3}, {%4,%5,%6,%7}, {%8,%9}, {%0,%1,%2,%3};"
        : "+f"(c[0]), "+f"(c[1]), "+f"(c[2]), "+f"(c[3])
        : "r"(a[0]), "r"(a[1]), "r"(a[2]), "r"(a[3]), "r"(b0), "r"(b1));
}
__device__ __forceinline__ void ldsm_x4(uint32_t* r, uint32_t addr) {
    asm volatile("ldmatrix.sync.aligned.m8n8.x4.shared.b16 {%0,%1,%2,%3}, [%4];"
                 : "=r"(r[0]), "=r"(r[1]), "=r"(r[2]), "=r"(r[3]) : "r"(addr));
}
__device__ __forceinline__ void ldsm_x4_t(uint32_t* r, uint32_t addr) {
    asm volatile("ldmatrix.sync.aligned.m8n8.x4.trans.shared.b16 {%0,%1,%2,%3}, [%4];"
                 : "=r"(r[0]), "=r"(r[1]), "=r"(r[2]), "=r"(r[3]) : "r"(addr));
}

// ---------------------------------------------------------------------------
// device bodies (verbatim from passing rounds)
// ---------------------------------------------------------------------------
__device__ void dev_prep(const int* __restrict__ cat_ids) {
    int c = threadIdx.x;
    if (c >= CC) return;
    int cnt = 0;
    for (int b = 0; b < BB; ++b)
        if (cat_ids[b] == c) g_cat_list[c * BB + cnt++] = b;
    g_cat_cnt[c] = cnt;
}

__device__ void dev_tau1(int b, const int* __restrict__ timesteps) {
    const int tid = threadIdx.x;
    const float t = (float)timesteps[b];
    const int half = HH / 2;
    const float scale = logf(10000.0f) / (float)half;
    for (int d = tid; d < HH; d += 256) {
        int j = (d < half) ? d : (d - half);
        float f = t * expf(-(float)j * scale);
        g_tau[b * HH + d] = (d < half) ? sinf(f) : cosf(f);
    }
}

__device__ void dev_actconv(int blk, const float* __restrict__ actions) {
    #pragma unroll
    for (int r = 0; r < 4; ++r) {
        int i = blk * 1024 + r * 256 + threadIdx.x;   // pair index, 131072 total
        float x = actions[2 * i], y = actions[2 * i + 1];
        uint32_t h, l;
        split_pair(x, y, h, l);
        ((uint32_t*)g_a0h)[i] = h;
        ((uint32_t*)g_a0l)[i] = l;
    }
}

// tau2 @256 threads: flat in [0,1024): bx = flat&1, cat = (flat>>1)&15, z = flat>>5
__device__ void dev_tau2(int flat, const float* __restrict__ W2, float* ts /*[8*TAU_KB]*/) {
    const int bx  = flat & 1;
    const int cat = (flat >> 1) & 15;
    const int z   = flat >> 5;
    const int tid = threadIdx.x;
    const int n2  = bx * 256 + tid;          // float2 column, 0..511
    const int cnt = g_cat_cnt[cat];
    if (cnt == 0) return;

    const int k0 = z * TAU_KB;
    const float* Wp = W2 + (size_t)cat * 2 * HH * HH
                         + (size_t)(HH + k0) * HH + 2 * n2;

    for (int base = 0; base < cnt; base += 8) {
        int nb = min(8, cnt - base);
        __syncthreads();
        for (int bl = 0; bl < nb; ++bl) {
            int bb = g_cat_list[cat * BB + base + bl];
            for (int d = tid; d < TAU_KB; d += 256)
                ts[bl * TAU_KB + d] = g_tau[bb * HH + k0 + d];
        }
        __syncthreads();
        float2 acc[8];
        #pragma unroll
        for (int bl = 0; bl < 8; ++bl) acc[bl] = make_float2(0.f, 0.f);
        #pragma unroll 4
        for (int k = 0; k < TAU_KB; ++k) {
            float2 w = *(const float2*)&Wp[(size_t)k * HH];
            #pragma unroll
            for (int bl = 0; bl < 8; ++bl) {
                acc[bl].x = fmaf(ts[bl * TAU_KB + k], w.x, acc[bl].x);
                acc[bl].y = fmaf(ts[bl * TAU_KB + k], w.y, acc[bl].y);
            }
        }
        for (int bl = 0; bl < nb; ++bl) {
            int bb = g_cat_list[cat * BB + base + bl];
            *(float2*)&g_part[((size_t)z * BB + bb) * HH + 2 * n2] = acc[bl];
        }
    }
}

// ---------------------------------------------------------------------------
// R12-proven split-bf16 mma layer body (inline B convert, A pre-split planes).
// smem arrays passed by pointer. 256 threads (2m x 4n warps, 32x32 each).
// ---------------------------------------------------------------------------
template <int K, int ACT, int ADDMODE, int OUTMODE>
__device__ void dev_layer12(int nt, int b,
          const __nv_bfloat16* __restrict__ Ahp,
          const __nv_bfloat16* __restrict__ Alp,
          const float* __restrict__ Wbase, size_t wstride,
          const float* __restrict__ addv,
          const int* __restrict__ cat_ids,
          float* __restrict__ outf,
          __nv_bfloat16* __restrict__ outh,
          __nv_bfloat16* __restrict__ outl,
          uint32_t* As_hi, uint32_t* As_lo,
          uint32_t* Bs_hi, uint32_t* Bs_lo) {
    const int tid  = threadIdx.x;
    const int lane = tid & 31;
    const int warp = tid >> 5;
    const int wm   = warp >> 2;   // 0..1
    const int wn   = warp & 3;    // 0..3
    const int c    = cat_ids[b];

    const float* W = Wbase + (size_t)c * wstride + nt * NT;
    const __nv_bfloat16* Ah = Ahp + (size_t)b * 64 * K;
    const __nv_bfloat16* Al = Alp + (size_t)b * 64 * K;

    const uint32_t sAh = smem_u32(As_hi), sAl = smem_u32(As_lo);
    const uint32_t sBh = smem_u32(Bs_hi), sBl = smem_u32(Bs_lo);

    float acc[2][4][4];
    #pragma unroll
    for (int i = 0; i < 2; ++i)
        #pragma unroll
        for (int j = 0; j < 4; ++j)
            #pragma unroll
            for (int q = 0; q < 4; ++q) acc[i][j][q] = 0.0f;

    constexpr int NCHUNK = K / KC;

    const int a_m  = tid >> 2;
    const int a_kq = tid & 3;
    uint4 pah, pal;
    float4 pb0[2], pb1[2];

    // prefetch chunk 0
    pah = *(const uint4*)&Ah[(size_t)a_m * K + a_kq * 8];
    pal = *(const uint4*)&Al[(size_t)a_m * K + a_kq * 8];
    #pragma unroll
    for (int r = 0; r < 2; ++r) {
        int i = tid + r * 256, nq = i & 31, kp = i >> 5;
        pb0[r] = *(const float4*)&W[(size_t)(kp * 2)     * HH + nq * 4];
        pb1[r] = *(const float4*)&W[(size_t)(kp * 2 + 1) * HH + nq * 4];
    }

    const int l15 = lane & 15, g16 = lane >> 4;

    for (int ch = 0; ch < NCHUNK; ++ch) {
        __syncthreads();   // previous iteration's frag reads complete

        // ---- STS A (pure copy) ----
        *(uint4*)&As_hi[a_m * 20 + a_kq * 4] = pah;
        *(uint4*)&As_lo[a_m * 20 + a_kq * 4] = pal;
        // ---- STS B (convert fp32 -> bf16 hi/lo) ----
        #pragma unroll
        for (int r = 0; r < 2; ++r) {
            int i = tid + r * 256, nq = i & 31, kp = i >> 5;
            float4 v0 = pb0[r], v1 = pb1[r];
            uint32_t h01, l01, h23, l23;
            split_pair(v0.x, v0.y, h01, l01);
            split_pair(v0.z, v0.w, h23, l23);
            int idx0 = (kp * 2) * 68 + nq * 2;
            *(uint2*)&Bs_hi[idx0] = make_uint2(h01, h23);
            *(uint2*)&Bs_lo[idx0] = make_uint2(l01, l23);
            split_pair(v1.x, v1.y, h01, l01);
            split_pair(v1.z, v1.w, h23, l23);
            int idx1 = (kp * 2 + 1) * 68 + nq * 2;
            *(uint2*)&Bs_hi[idx1] = make_uint2(h01, h23);
            *(uint2*)&Bs_lo[idx1] = make_uint2(l01, l23);
        }
        __syncthreads();

        // ---- prefetch next chunk (overlaps MMA below) ----
        if (ch + 1 < NCHUNK) {
            int k0 = (ch + 1) * KC;
            pah = *(const uint4*)&Ah[(size_t)a_m * K + k0 + a_kq * 8];
            pal = *(const uint4*)&Al[(size_t)a_m * K + k0 + a_kq * 8];
            #pragma unroll
            for (int r = 0; r < 2; ++r) {
                int i = tid + r * 256, nq = i & 31, kp = i >> 5;
                pb0[r] = *(const float4*)&W[(size_t)(k0 + kp * 2)     * HH + nq * 4];
                pb1[r] = *(const float4*)&W[(size_t)(k0 + kp * 2 + 1) * HH + nq * 4];
            }
        }

        // ---- MMA phase: two k16 steps, ldmatrix frags ----
        #pragma unroll
        for (int t = 0; t < 2; ++t) {
            uint32_t Ahf[2][4], Alf[2][4];
            #pragma unroll
            for (int ms = 0; ms < 2; ++ms) {
                uint32_t abyte = (wm * 32 + ms * 16 + l15) * 80 + t * 32 + g16 * 16;
                ldsm_x4(Ahf[ms], sAh + abyte);
                ldsm_x4(Alf[ms], sAl + abyte);
            }
            uint32_t Bh[2][4], Bl[2][4];
            #pragma unroll
            for (int nfp = 0; nfp < 2; ++nfp) {
                int kr = t * 16 + l15;
                uint32_t bbyte = kr * 272 + (wn * 32 + nfp * 16 + g16 * 8) * 2;
                ldsm_x4_t(Bh[nfp], sBh + bbyte);
                ldsm_x4_t(Bl[nfp], sBl + bbyte);
            }
            #pragma unroll
            for (int nf = 0; nf < 4; ++nf) {
                uint32_t bh0 = Bh[nf >> 1][(nf & 1) * 2];
                uint32_t bh1 = Bh[nf >> 1][(nf & 1) * 2 + 1];
                uint32_t bl0 = Bl[nf >> 1][(nf & 1) * 2];
                uint32_t bl1 = Bl[nf >> 1][(nf & 1) * 2 + 1];
                #pragma unroll
                for (int ms = 0; ms < 2; ++ms) {
                    mma_bf16(acc[ms][nf], Ahf[ms], bh0, bh1);   // hi*hi
                    mma_bf16(acc[ms][nf], Ahf[ms], bl0, bl1);   // hi*lo
                    mma_bf16(acc[ms][nf], Alf[ms], bh0, bh1);   // lo*hi
                }
            }
        }
    }

    // ---- epilogue ----
    const float* addp = (ADDMODE == 0) ? (addv + (size_t)c * HH)
                                       : (addv + (size_t)b * HH);
    const int lr = lane >> 2;
    const int lc = lane & 3;
    #pragma unroll
    for (int ms = 0; ms < 2; ++ms) {
        int r0 = wm * 32 + ms * 16 + lr;
        #pragma unroll
        for (int nf = 0; nf < 4; ++nf) {
            int ncol = nt * NT + wn * 32 + nf * 8 + lc * 2;
            float bv0 = addp[ncol], bv1 = addp[ncol + 1];
            float v0 = acc[ms][nf][0] + bv0;
            float v1 = acc[ms][nf][1] + bv1;
            float v2 = acc[ms][nf][2] + bv0;
            float v3 = acc[ms][nf][3] + bv1;
            if (ACT == 1) {
                v0 = v0 / (1.0f + expf(-v0));
                v1 = v1 / (1.0f + expf(-v1));
                v2 = v2 / (1.0f + expf(-v2));
                v3 = v3 / (1.0f + expf(-v3));
            }
            size_t o0 = ((size_t)b * TT + r0)     * HH + ncol;
            size_t o1 = ((size_t)b * TT + r0 + 8) * HH + ncol;
            if (OUTMODE == 0) {
                *(float2*)&outf[o0] = make_float2(v0, v1);
                *(float2*)&outf[o1] = make_float2(v2, v3);
            } else {
                uint32_t h, l;
                split_pair(v0, v1, h, l);
                *(uint32_t*)&outh[o0] = h;
                *(uint32_t*)&outl[o0] = l;
                split_pair(v2, v3, h, l);
                *(uint32_t*)&outh[o1] = h;
                *(uint32_t*)&outl[o1] = l;
            }
        }
    }
}

// ---------------------------------------------------------------------------
// Launch A: prep | tau1 | actconv.  grid(193), 256 thr.
// ---------------------------------------------------------------------------
__global__ void stepA_kernel(const int* __restrict__ cat_ids,
                             const int* __restrict__ timesteps,
                             const float* __restrict__ actions) {
    const int x = blockIdx.x;
    if (x == 0) {
        dev_prep(cat_ids);
    } else if (x < 65) {
        dev_tau1(x - 1, timesteps);
    } else {
        dev_actconv(x - 65, actions);
    }
}

// ---------------------------------------------------------------------------
// Launch B: layer1 | tau2.  grid(24, 64), 256 thr.
//   x < 8  : layer1 tile (nt=x, b=y)
//   x >= 8 : tau2 flat = (x-8)*64 + y  (1024 blocks)
// ---------------------------------------------------------------------------
__global__ void __launch_bounds__(256, 2)
stepB_kernel(const float* __restrict__ W1,
             const float* __restrict__ b1,
             const float* __restrict__ W2,
             const int* __restrict__ cat_ids) {
    __shared__ __align__(16) uint32_t As_hi[64 * 20];
    __shared__ __align__(16) uint32_t As_lo[64 * 20];
    __shared__ __align__(16) uint32_t Bs_hi[32 * 68];
    __shared__ __align__(16) uint32_t Bs_lo[32 * 68];
    __shared__ float ts[8 * TAU_KB];

    const int x = blockIdx.x, y = blockIdx.y;
    if (x < 8) {
        dev_layer12<AA, 0, 0, 1>(x, y, g_a0h, g_a0l, W1, (size_t)AA * HH,
                                 b1, cat_ids, nullptr, g_a1h, g_a1l,
                                 As_hi, As_lo, Bs_hi, Bs_lo);
    } else {
        dev_tau2((x - 8) * 64 + y, W2, ts);
    }
}

// ---------------------------------------------------------------------------
// tau3: deterministic reduce of partials + bias -> g_tauc. grid(4,64), 256.
// ---------------------------------------------------------------------------
__global__ void tau3_kernel(const int* __restrict__ cat_ids,
                            const float* __restrict__ b2) {
    const int b = blockIdx.y;
    const int n = blockIdx.x * 256 + threadIdx.x;
    const int c = cat_ids[b];
    float s = b2[c * HH + n];
    #pragma unroll
    for (int z = 0; z < KSPLIT; ++z)
        s += g_part[((size_t)z * BB + b) * HH + n];
    g_tauc[b * HH + n] = s;
}

// ---------------------------------------------------------------------------
// Standalone R12-style layer kernel (layers 2 and 3). grid(8, 64), 256 thr.
// ---------------------------------------------------------------------------
template <int K, int ACT, int ADDMODE, int OUTMODE>
__global__ void __launch_bounds__(256, 2)
mma12_kernel(const __nv_bfloat16* __restrict__ Ahp,
             const __nv_bfloat16* __restrict__ Alp,
             const float* __restrict__ Wbase, size_t wstride,
             const float* __restrict__ addv,
             const int* __restrict__ cat_ids,
             float* __restrict__ outf,
             __nv_bfloat16* __restrict__ outh,
             __nv_bfloat16* __restrict__ outl) {
    __shared__ __align__(16) uint32_t As_hi[64 * 20];
    __shared__ __align__(16) uint32_t As_lo[64 * 20];
    __shared__ __align__(16) uint32_t Bs_hi[32 * 68];
    __shared__ __align__(16) uint32_t Bs_lo[32 * 68];
    dev_layer12<K, ACT, ADDMODE, OUTMODE>(blockIdx.x, blockIdx.y,
        Ahp, Alp, Wbase, wstride, addv, cat_ids, outf, outh, outl,
        As_hi, As_lo, Bs_hi, Bs_lo);
}

extern "C" void kernel_launch(void* const* d_in, const int* in_sizes, int n_in,
                              void* d_out, int out_size) {
    const float* actions   = (const float*)d_in[0];
    const int*   timesteps = (const int*)d_in[1];
    const int*   cat_ids   = (const int*)d_in[2];
    const float* W1 = (const float*)d_in[3];
    const float* b1 = (const float*)d_in[4];
    const float* W2 = (const float*)d_in[5];
    const float* b2 = (const float*)d_in[6];
    const float* W3 = (const float*)d_in[7];
    const float* b3 = (const float*)d_in[8];
    float* out = (float*)d_out;

    __nv_bfloat16 *a1h, *a1l, *a2h, *a2l;
    float *tauc;
    cudaGetSymbolAddress((void**)&a1h, g_a1h);
    cudaGetSymbolAddress((void**)&a1l, g_a1l);
    cudaGetSymbolAddress((void**)&a2h, g_a2h);
    cudaGetSymbolAddress((void**)&a2l, g_a2l);
    cudaGetSymbolAddress((void**)&tauc, g_tauc);

    // A: prep | tau1 | actconv
    stepA_kernel<<<193, 256>>>(cat_ids, timesteps, actions);

    // B: layer1 | tau2
    stepB_kernel<<<dim3(24, 64), 256>>>(W1, b1, W2, cat_ids);

    // tau3
    tau3_kernel<<<dim3(4, 64), 256>>>(cat_ids, b2);

    // layer 2: h planes = swish(aemb @ W2[:1024] + tauc)
    mma12_kernel<HH, 1, 1, 1><<<dim3(8, 64), 256>>>(
        a1h, a1l, W2, (size_t)2 * HH * HH, tauc, cat_ids, nullptr, a2h, a2l);

    // layer 3: out fp32 = h @ W3 + b3
    mma12_kernel<HH, 0, 0, 0><<<dim3(8, 64), 256>>>(
        a2h, a2l, W3, (size_t)HH * HH, b3, cat_ids, out, nullptr, nullptr);
}